// round 15
// baseline (speedup 1.0000x reference)
#include <cuda_runtime.h>
#include <cuda_bf16.h>
#include <cstdint>

#define NN 13
#define HD 128
#define NLAYER 8
#define NJ 17
#define DMAX 33
#define OBSD 348
#define SPC 8
#define MREAL 104
#define MPAD 128
#define NTHREADS 512
#define PHW 68                 // x hi/lo plane row stride (u32); 68%32=4 -> LDSM conflict-free
#define ZW 132                 // z fp32 plane row stride (floats)
#define HHW 68
#define BTOT 16384

// fragment-packed bf16 hi/lo W images: [k16 0..7]=W_top rows, [k16 8..15]=W_bot rows
__device__ __align__(16) uint4 g_Bfrag[NLAYER][16 * 16 * 32];
__device__ __align__(16) uint4 g_W2frag[NN][8 * 16 * 32];
__device__ __align__(16) uint32_t g_xh[(size_t)BTOT * NN * 64];
__device__ __align__(16) uint32_t g_xl[(size_t)BTOT * NN * 64];

__constant__ int c_feat[NN][DMAX] = {
  {0,1,2,3,4,22,23,24,25,26,27,45,46,47,48,49,50,51,52,53,54,175,176,177,178,179,180,270,271,272,273,274,275},
  {5,6,28,29,55,56,57,58,59,60,61,62,63,64,181,182,183,184,185,186,276,277,278,279,280,281,0,0,0,0,0,0,0},
  {7,30,65,66,67,68,69,70,71,72,73,74,187,188,189,190,191,192,253,254,255,282,283,284,285,286,287,0,0,0,0,0,0},
  {8,9,10,11,31,32,33,34,75,76,77,78,79,80,81,82,83,84,193,194,195,196,197,198,256,257,258,288,289,290,291,292,293},
  {11,34,85,86,87,88,89,90,91,92,93,94,199,200,201,202,203,204,259,294,295,296,297,298,299,0,0,0,0,0,0,0,0},
  {95,96,97,98,99,100,101,102,103,104,205,206,207,208,209,210,300,301,302,303,304,305,0,0,0,0,0,0,0,0,0,0,0},
  {12,13,14,15,35,36,37,38,105,106,107,108,109,110,111,112,113,114,211,212,213,214,215,216,260,261,262,306,307,308,309,310,311},
  {15,38,115,116,117,118,119,120,121,122,123,124,217,218,219,220,221,222,263,312,313,314,315,316,317,0,0,0,0,0,0,0,0},
  {125,126,127,128,129,130,131,132,133,134,223,224,225,226,227,228,318,319,320,321,322,323,0,0,0,0,0,0,0,0,0,0,0},
  {16,17,18,39,40,41,135,136,137,138,139,140,141,142,143,144,229,230,231,232,233,234,264,265,324,325,326,327,328,329,0,0,0},
  {18,41,145,146,147,148,149,150,151,152,153,154,235,236,237,238,239,240,266,330,331,332,333,334,335,0,0,0,0,0,0,0,0},
  {19,20,21,42,43,44,155,156,157,158,159,160,161,162,163,164,241,242,243,244,245,246,267,268,336,337,338,339,340,341,0,0,0},
  {21,44,165,166,167,168,169,170,171,172,173,174,247,248,249,250,251,252,269,342,343,344,345,346,347,0,0,0,0,0,0,0,0}
};
__constant__ int c_dcnt[NN] = {33,26,27,33,25,22,33,25,22,30,25,30,25};
__constant__ int c_nbr[NN][3] = {
  {1,9,11},{0,2,0},{1,3,6},{2,4,0},{3,5,0},{4,0,0},{2,7,0},
  {6,8,0},{7,0,0},{0,10,0},{9,0,0},{0,12,0},{11,0,0}
};
__constant__ int c_deg[NN] = {3,2,3,2,2,1,2,2,1,2,1,2,1};
__constant__ int c_jm0[NJ] = {1,1,1,2,2,2,3,2,2,2,6,0,0,9,0,0,11};
__constant__ int c_jm1[NJ] = {2,2,2,3,3,3,4,6,6,6,7,9,9,10,11,11,12};

__device__ __forceinline__ float eluf(float x) { return x > 0.0f ? x : expm1f(x); }
__device__ __forceinline__ unsigned long long pk2(float lo, float hi) {
    unsigned long long r;
    asm("mov.b64 %0, {%1, %2};" : "=l"(r) : "f"(lo), "f"(hi));
    return r;
}
__device__ __forceinline__ void upk2(unsigned long long v, float& lo, float& hi) {
    asm("mov.b64 {%0, %1}, %2;" : "=f"(lo), "=f"(hi) : "l"(v));
}
__device__ __forceinline__ void fma2(unsigned long long& d, unsigned long long a, unsigned long long b) {
    asm("fma.rn.f32x2 %0, %1, %2, %0;" : "+l"(d) : "l"(a), "l"(b));
}
__device__ __forceinline__ uint32_t cvt_bf16x2(float hi, float lo) {
    uint32_t r;
    asm("cvt.rn.bf16x2.f32 %0, %1, %2;" : "=r"(r) : "f"(hi), "f"(lo));
    return r;
}
__device__ __forceinline__ void split_pair(float2 f, uint32_t& hi, uint32_t& lo) {
    uint32_t u0 = __float_as_uint(f.x), u1 = __float_as_uint(f.y);
    hi = __byte_perm(u0, u1, 0x7632);
    float r0 = f.x - __uint_as_float(u0 & 0xFFFF0000u);
    float r1 = f.y - __uint_as_float(u1 & 0xFFFF0000u);
    lo = cvt_bf16x2(r1, r0);
}
__device__ __forceinline__ float2 rec2(uint32_t h, uint32_t l) {
    float2 fh = __bfloat1622float2(*reinterpret_cast<__nv_bfloat162*>(&h));
    float2 fl = __bfloat1622float2(*reinterpret_cast<__nv_bfloat162*>(&l));
    return make_float2(fh.x + fl.x, fh.y + fl.y);
}
__device__ __forceinline__ void mma_bf16(float* c, const uint32_t* a, uint32_t b0, uint32_t b1) {
    asm("mma.sync.aligned.m16n8k16.row.col.f32.bf16.bf16.f32 "
        "{%0,%1,%2,%3}, {%4,%5,%6,%7}, {%8,%9}, {%0,%1,%2,%3};"
        : "+f"(c[0]), "+f"(c[1]), "+f"(c[2]), "+f"(c[3])
        : "r"(a[0]), "r"(a[1]), "r"(a[2]), "r"(a[3]), "r"(b0), "r"(b1));
}
__device__ __forceinline__ void ldsm4(uint32_t* r, uint32_t addr) {
    asm volatile("ldmatrix.sync.aligned.m8n8.x4.shared.b16 {%0,%1,%2,%3}, [%4];"
        : "=r"(r[0]), "=r"(r[1]), "=r"(r[2]), "=r"(r[3]) : "r"(addr));
}
__device__ __forceinline__ void cpa16(uint32_t s, const void* g) {
    asm volatile("cp.async.cg.shared.global [%0], [%1], 16;\n" :: "r"(s), "l"(g));
}
__device__ __forceinline__ void cpa_commit() { asm volatile("cp.async.commit_group;\n" ::: "memory"); }
__device__ __forceinline__ void cpa_wait0()  { asm volatile("cp.async.wait_group 0;\n" ::: "memory"); }

// ======== prep kernels (unchanged layouts) ========
__global__ void prep_kernel(const float* __restrict__ Wmsg) {
    int idx = blockIdx.x * 256 + threadIdx.x;
    int lane = idx & 31;
    int nt   = (idx >> 5) & 15;
    int k16  = (idx >> 9) & 15;
    int l    = idx >> 13;
    if (l >= NLAYER) return;
    int n  = nt * 8 + (lane >> 2);
    int q2 = (lane & 3) * 2;
    int kb = k16 * 16;
    const float* W = Wmsg + (size_t)l * 256 * HD;
    float w0 = W[(kb + q2) * HD + n];
    float w1 = W[(kb + q2 + 1) * HD + n];
    float w2 = W[(kb + 8 + q2) * HD + n];
    float w3 = W[(kb + 8 + q2 + 1) * HD + n];
    __nv_bfloat162 h0 = __floats2bfloat162_rn(w0, w1);
    __nv_bfloat162 h1 = __floats2bfloat162_rn(w2, w3);
    __nv_bfloat162 l0 = __floats2bfloat162_rn(w0 - __bfloat162float(h0.x), w1 - __bfloat162float(h0.y));
    __nv_bfloat162 l1 = __floats2bfloat162_rn(w2 - __bfloat162float(h1.x), w3 - __bfloat162float(h1.y));
    uint4 v;
    v.x = *reinterpret_cast<uint32_t*>(&h0);
    v.y = *reinterpret_cast<uint32_t*>(&h1);
    v.z = *reinterpret_cast<uint32_t*>(&l0);
    v.w = *reinterpret_cast<uint32_t*>(&l1);
    g_Bfrag[l][(k16 * 16 + nt) * 32 + lane] = v;
}
__global__ void prep2_kernel(const float* __restrict__ W2) {
    int idx = blockIdx.x * 256 + threadIdx.x;
    int lane = idx & 31;
    int nt   = (idx >> 5) & 15;
    int k16  = (idx >> 9) & 7;
    int n    = idx >> 12;
    if (n >= NN) return;
    int nc = nt * 8 + (lane >> 2);
    int q2 = (lane & 3) * 2;
    int kb = k16 * 16;
    const float* W = W2 + (size_t)n * HD * HD;
    float w0 = W[(kb + q2) * HD + nc];
    float w1 = W[(kb + q2 + 1) * HD + nc];
    float w2 = W[(kb + 8 + q2) * HD + nc];
    float w3 = W[(kb + 8 + q2 + 1) * HD + nc];
    __nv_bfloat162 h0 = __floats2bfloat162_rn(w0, w1);
    __nv_bfloat162 h1 = __floats2bfloat162_rn(w2, w3);
    __nv_bfloat162 l0 = __floats2bfloat162_rn(w0 - __bfloat162float(h0.x), w1 - __bfloat162float(h0.y));
    __nv_bfloat162 l1 = __floats2bfloat162_rn(w2 - __bfloat162float(h1.x), w3 - __bfloat162float(h1.y));
    uint4 v;
    v.x = *reinterpret_cast<uint32_t*>(&h0);
    v.y = *reinterpret_cast<uint32_t*>(&h1);
    v.z = *reinterpret_cast<uint32_t*>(&l0);
    v.w = *reinterpret_cast<uint32_t*>(&l1);
    g_W2frag[n][(k16 * 16 + nt) * 32 + lane] = v;
}

// ======== kernel A: encoder (unchanged from R14) ========
__global__ __launch_bounds__(NTHREADS, 1)
void enc_kernel(const float* __restrict__ obs,
                const float* __restrict__ W1, const float* __restrict__ b1,
                const float* __restrict__ b2)
{
    extern __shared__ __align__(16) uint32_t smu[];
    uint32_t* hh = smu;
    uint32_t* hl = smu + 128 * HHW;
    float* xn = (float*)(smu + 2 * 128 * HHW);

    const int tid  = threadIdx.x;
    const int lane = tid & 31;
    const int ty   = tid >> 5;
    const int n    = blockIdx.x >> 7;
    const int s0   = (blockIdx.x & 127) * 128;

    const uint32_t hh_a = (uint32_t)__cvta_generic_to_shared(hh);
    const uint32_t hl_a = (uint32_t)__cvta_generic_to_shared(hl);

    const int dc = c_dcnt[n];
    for (int i = tid; i < 128 * dc; i += NTHREADS) {
        int s = i / dc, d = i - s * dc;
        xn[s * 36 + d] = obs[(size_t)(s0 + s) * OBSD + c_feat[n][d]];
    }
    __syncthreads();

    {
        unsigned long long acc[8][2];
        const unsigned long long* bp = (const unsigned long long*)(b1 + n * HD);
        unsigned long long a0 = bp[lane], a1 = bp[lane + 32];
        #pragma unroll
        for (int s = 0; s < 8; ++s) { acc[s][0] = a0; acc[s][1] = a1; }
        #pragma unroll 1
        for (int d = 0; d < dc; ++d) {
            const unsigned long long* wr = (const unsigned long long*)(W1 + (n * DMAX + d) * HD);
            unsigned long long w0 = wr[lane], w1 = wr[lane + 32];
            #pragma unroll
            for (int s = 0; s < 8; ++s) {
                float xe = xn[(ty * 8 + s) * 36 + d];
                unsigned long long p = pk2(xe, xe);
                fma2(acc[s][0], p, w0); fma2(acc[s][1], p, w1);
            }
        }
        #pragma unroll
        for (int s = 0; s < 8; ++s) {
            const int row = ty * 8 + s;
            float lo, hi;
            uint32_t ph, pl;
            upk2(acc[s][0], lo, hi);
            split_pair(make_float2(eluf(lo), eluf(hi)), ph, pl);
            hh[row * HHW + lane] = ph; hl[row * HHW + lane] = pl;
            upk2(acc[s][1], lo, hi);
            split_pair(make_float2(eluf(lo), eluf(hi)), ph, pl);
            hh[row * HHW + 32 + lane] = ph; hl[row * HHW + 32 + lane] = pl;
        }
    }
    __syncthreads();

    const int mwarp = ty >> 2;
    const int nwarp = ty & 3;
    const int qr = lane >> 2;
    const int q2c = lane & 3;

    uint32_t lb_h[2], lb_l[2];
    {
        int seg = lane >> 3, rr = lane & 7;
        #pragma unroll
        for (int t = 0; t < 2; ++t) {
            int row = mwarp * 32 + t * 16 + (seg & 1) * 8 + rr;
            uint32_t off = (uint32_t)row * (HHW * 4) + (uint32_t)(seg >> 1) * 16;
            lb_h[t] = hh_a + off;
            lb_l[t] = hl_a + off;
        }
    }

    float C[2][4][4];
    #pragma unroll
    for (int t = 0; t < 2; ++t)
        #pragma unroll
        for (int nt = 0; nt < 4; ++nt)
            #pragma unroll
            for (int e = 0; e < 4; ++e) C[t][nt][e] = 0.0f;

    const uint4* Bf = g_W2frag[n];
    #pragma unroll 1
    for (int k16 = 0; k16 < 8; ++k16) {
        const uint32_t kboff = (uint32_t)k16 * 32;
        uint32_t Ah[2][4], Al[2][4];
        #pragma unroll
        for (int t = 0; t < 2; ++t) {
            ldsm4(Ah[t], lb_h[t] + kboff);
            ldsm4(Al[t], lb_l[t] + kboff);
        }
        #pragma unroll
        for (int nt = 0; nt < 4; ++nt) {
            uint4 bv = Bf[(k16 * 16 + nwarp * 4 + nt) * 32 + lane];
            #pragma unroll
            for (int t = 0; t < 2; ++t) {
                mma_bf16(C[t][nt], Ah[t], bv.x, bv.y);
                mma_bf16(C[t][nt], Al[t], bv.x, bv.y);
                mma_bf16(C[t][nt], Ah[t], bv.z, bv.w);
            }
        }
    }
    #pragma unroll
    for (int t = 0; t < 2; ++t) {
        const int r0 = mwarp * 32 + t * 16 + qr;
        #pragma unroll
        for (int nt = 0; nt < 4; ++nt) {
            const int c2 = nwarp * 16 + nt * 4 + q2c;
            float2 bb = *(const float2*)(b2 + n * HD + 2 * c2);
            uint32_t ph, pl;
            size_t ga = ((size_t)(s0 + r0) * NN + n) * 64 + c2;
            split_pair(make_float2(C[t][nt][0] + bb.x, C[t][nt][1] + bb.y), ph, pl);
            g_xh[ga] = ph; g_xl[ga] = pl;
            size_t gb = ((size_t)(s0 + r0 + 8) * NN + n) * 64 + c2;
            split_pair(make_float2(C[t][nt][2] + bb.x, C[t][nt][3] + bb.y), ph, pl);
            g_xh[gb] = ph; g_xl[gb] = pl;
        }
    }
}

// ======== kernel B: y/z-split message passing ========
__global__ __launch_bounds__(NTHREADS)
void gnn_mma_kernel(const float* __restrict__ bmsg,
                    const float* __restrict__ Wout, const float* __restrict__ bout,
                    float* __restrict__ out)
{
    extern __shared__ __align__(16) uint32_t smu[];
    uint32_t* xh = smu;                           // [128][68] x hi plane
    uint32_t* xl = smu + MPAD * PHW;              // x lo plane
    float* zf = (float*)(smu + 2 * MPAD * PHW);   // [128][132] z fp32
    float* sbias = zf + MPAD * ZW;                // 1024 floats

    const int tid  = threadIdx.x;
    const int lane = tid & 31;
    const int ty   = tid >> 5;
    const int base_s = blockIdx.x * SPC;

    const uint32_t xh_a = (uint32_t)__cvta_generic_to_shared(xh);
    const uint32_t xl_a = (uint32_t)__cvta_generic_to_shared(xl);

    // ==== load x0 planes + bias + zero pads ====
    {
        const uint32_t* gh = g_xh + (size_t)base_s * NN * 64;
        const uint32_t* gl = g_xl + (size_t)base_s * NN * 64;
        for (int i = tid; i < MREAL * 16; i += NTHREADS) {
            int r = i >> 4, c4 = (i & 15) * 4;
            cpa16(xh_a + (uint32_t)(r * PHW + c4) * 4, gh + r * 64 + c4);
            cpa16(xl_a + (uint32_t)(r * PHW + c4) * 4, gl + r * 64 + c4);
        }
        cpa_commit();
        if (tid < 256) ((float4*)sbias)[tid] = ((const float4*)bmsg)[tid];
        for (int i = tid; i < (MPAD - MREAL) * PHW; i += NTHREADS) {
            xh[MREAL * PHW + i] = 0u;
            xl[MREAL * PHW + i] = 0u;
        }
    }
    cpa_wait0();

    const int mwarp = ty >> 2;
    const int nwarp = ty & 3;
    const int qr = lane >> 2;
    const int q2c = lane & 3;

    uint32_t lbase_h[2], lbase_l[2];
    {
        int seg = lane >> 3, rr = lane & 7;
        #pragma unroll
        for (int t = 0; t < 2; ++t) {
            int row = mwarp * 32 + t * 16 + (seg & 1) * 8 + rr;
            uint32_t off = (uint32_t)row * (PHW * 4) + (uint32_t)(seg >> 1) * 16;
            lbase_h[t] = xh_a + off;
            lbase_l[t] = xl_a + off;
        }
    }

    // per-row neighbor info for the combine epilogue (4 rows per thread)
    int rown[2], rows13[2], rowdg[2];
    #pragma unroll
    for (int t = 0; t < 2; ++t) {
        int m = mwarp * 32 + t * 16 + qr;      // row r0; r0+8 handled via +8 below
        rown[t] = m % NN;
        rows13[t] = m - rown[t];
        rowdg[t] = c_deg[rown[t]];
    }
    int rown2[2], rows13b[2], rowdg2[2];
    #pragma unroll
    for (int t = 0; t < 2; ++t) {
        int m = mwarp * 32 + t * 16 + qr + 8;
        rown2[t] = m % NN;
        rows13b[t] = m - rown2[t];
        rowdg2[t] = c_deg[rown2[t]];
    }

    for (int l = 0; l < NLAYER; ++l) {
        const uint4* Bl = g_Bfrag[l];

        __syncthreads();   // x planes ready (initial load or previous combine)

        float Cy[2][4][4], Cz[2][4][4];
        #pragma unroll
        for (int t = 0; t < 2; ++t)
            #pragma unroll
            for (int nt = 0; nt < 4; ++nt)
                #pragma unroll
                for (int e = 0; e < 4; ++e) { Cy[t][nt][e] = 0.0f; Cz[t][nt][e] = 0.0f; }

        #pragma unroll 2
        for (int k16 = 0; k16 < 8; ++k16) {
            const uint32_t kboff = (uint32_t)k16 * 32;
            uint32_t Ah[2][4], Al[2][4];
            #pragma unroll
            for (int t = 0; t < 2; ++t) {
                ldsm4(Ah[t], lbase_h[t] + kboff);
                ldsm4(Al[t], lbase_l[t] + kboff);
            }
            // B fragments: W_top at k16, W_bot at 8+k16 (direct LDG, L2-resident)
            uint4 by[4], bz[4];
            #pragma unroll
            for (int nt = 0; nt < 4; ++nt) {
                by[nt] = Bl[(k16 * 16 + nwarp * 4 + nt) * 32 + lane];
                bz[nt] = Bl[((8 + k16) * 16 + nwarp * 4 + nt) * 32 + lane];
            }
            #pragma unroll
            for (int nt = 0; nt < 4; ++nt) {
                #pragma unroll
                for (int t = 0; t < 2; ++t) {
                    mma_bf16(Cy[t][nt], Ah[t], by[nt].x, by[nt].y);
                    mma_bf16(Cy[t][nt], Al[t], by[nt].x, by[nt].y);
                    mma_bf16(Cy[t][nt], Ah[t], by[nt].z, by[nt].w);
                    mma_bf16(Cz[t][nt], Ah[t], bz[nt].x, bz[nt].y);
                    mma_bf16(Cz[t][nt], Al[t], bz[nt].x, bz[nt].y);
                    mma_bf16(Cz[t][nt], Ah[t], bz[nt].z, bz[nt].w);
                }
            }
        }

        // store z (fp32) to SMEM
        #pragma unroll
        for (int t = 0; t < 2; ++t) {
            const int r0 = mwarp * 32 + t * 16 + qr;
            #pragma unroll
            for (int nt = 0; nt < 4; ++nt) {
                const int f = (nwarp * 16 + nt * 4 + q2c) * 2;
                *(float2*)(zf + r0 * ZW + f)       = make_float2(Cz[t][nt][0], Cz[t][nt][1]);
                *(float2*)(zf + (r0 + 8) * ZW + f) = make_float2(Cz[t][nt][2], Cz[t][nt][3]);
            }
        }
        __syncthreads();   // z visible; all mainloop x-plane reads done

        // combine: x' = elu(y + sum_nb z[nb] + bias) -> x planes
        #pragma unroll
        for (int t = 0; t < 2; ++t) {
            const int r0 = mwarp * 32 + t * 16 + qr;
            if (r0 < MREAL) {
                const float* zb0 = zf + (rows13[t] + c_nbr[rown[t]][0]) * ZW;
                const float* zb1 = zf + (rows13[t] + c_nbr[rown[t]][1]) * ZW;
                const float* zb2 = zf + (rows13[t] + c_nbr[rown[t]][2]) * ZW;
                const int dg = rowdg[t];
                #pragma unroll
                for (int nt = 0; nt < 4; ++nt) {
                    const int c2 = nwarp * 16 + nt * 4 + q2c;
                    const int f = 2 * c2;
                    float2 bb = *(const float2*)(sbias + l * HD + f);
                    float2 zs = *(const float2*)(zb0 + f);
                    if (dg > 1) { float2 v = *(const float2*)(zb1 + f); zs.x += v.x; zs.y += v.y; }
                    if (dg > 2) { float2 v = *(const float2*)(zb2 + f); zs.x += v.x; zs.y += v.y; }
                    uint32_t ph, pl;
                    split_pair(make_float2(eluf(Cy[t][nt][0] + zs.x + bb.x),
                                           eluf(Cy[t][nt][1] + zs.y + bb.y)), ph, pl);
                    xh[r0 * PHW + c2] = ph; xl[r0 * PHW + c2] = pl;
                }
            }
            const int r1 = r0 + 8;
            if (r1 < MREAL) {
                const float* zb0 = zf + (rows13b[t] + c_nbr[rown2[t]][0]) * ZW;
                const float* zb1 = zf + (rows13b[t] + c_nbr[rown2[t]][1]) * ZW;
                const float* zb2 = zf + (rows13b[t] + c_nbr[rown2[t]][2]) * ZW;
                const int dg = rowdg2[t];
                #pragma unroll
                for (int nt = 0; nt < 4; ++nt) {
                    const int c2 = nwarp * 16 + nt * 4 + q2c;
                    const int f = 2 * c2;
                    float2 bb = *(const float2*)(sbias + l * HD + f);
                    float2 zs = *(const float2*)(zb0 + f);
                    if (dg > 1) { float2 v = *(const float2*)(zb1 + f); zs.x += v.x; zs.y += v.y; }
                    if (dg > 2) { float2 v = *(const float2*)(zb2 + f); zs.x += v.x; zs.y += v.y; }
                    uint32_t ph, pl;
                    split_pair(make_float2(eluf(Cy[t][nt][2] + zs.x + bb.x),
                                           eluf(Cy[t][nt][3] + zs.y + bb.y)), ph, pl);
                    xh[r1 * PHW + c2] = ph; xl[r1 * PHW + c2] = pl;
                }
            }
        }
    }
    __syncthreads();

    // ==== joint readout ====
    for (int t = ty; t < SPC * NJ; t += 16) {
        int s = t / NJ, j = t - s * NJ;
        const int ra = (s * NN + c_jm0[j]) * PHW;
        const int rb = (s * NN + c_jm1[j]) * PHW;
        const float* wj = Wout + j * 2 * HD;
        float2 a0 = rec2(xh[ra + lane], xl[ra + lane]);
        float2 a1 = rec2(xh[ra + 32 + lane], xl[ra + 32 + lane]);
        float2 b0 = rec2(xh[rb + lane], xl[rb + lane]);
        float2 b1v = rec2(xh[rb + 32 + lane], xl[rb + 32 + lane]);
        float2 w0 = *(const float2*)(wj + 2 * lane);
        float2 w1 = *(const float2*)(wj + 64 + 2 * lane);
        float2 w2 = *(const float2*)(wj + HD + 2 * lane);
        float2 w3 = *(const float2*)(wj + HD + 64 + 2 * lane);
        float sum = a0.x * w0.x + a0.y * w0.y + a1.x * w1.x + a1.y * w1.y
                  + b0.x * w2.x + b0.y * w2.y + b1v.x * w3.x + b1v.y * w3.y;
        #pragma unroll
        for (int o = 16; o; o >>= 1)
            sum += __shfl_xor_sync(0xffffffffu, sum, o);
        if (lane == 0)
            out[(size_t)(base_s + s) * NJ + j] = sum + bout[j];
    }
}

extern "C" void kernel_launch(void* const* d_in, const int* in_sizes, int n_in,
                              void* d_out, int out_size) {
    const float* obs  = (const float*)d_in[0];
    const float* W1   = (const float*)d_in[1];
    const float* b1   = (const float*)d_in[2];
    const float* W2   = (const float*)d_in[3];
    const float* b2   = (const float*)d_in[4];
    const float* Wmsg = (const float*)d_in[5];
    const float* bmsg = (const float*)d_in[6];
    const float* Wout = (const float*)d_in[7];
    const float* bout = (const float*)d_in[8];
    float* out = (float*)d_out;

    prep_kernel<<<NLAYER * 16 * 16 * 32 / 256, 256>>>(Wmsg);
    prep2_kernel<<<(NN * 8 * 16 * 32 + 255) / 256, 256>>>(W2);

    int B = in_sizes[0] / OBSD;

    size_t smemA = (size_t)(2 * 128 * HHW * 4 + 128 * 36 * 4);   // 88,064 B
    cudaFuncSetAttribute(enc_kernel, cudaFuncAttributeMaxDynamicSharedMemorySize, (int)smemA);
    enc_kernel<<<NN * (B / 128), NTHREADS, smemA>>>(obs, W1, b1, b2);

    int nblk = B / SPC;
    // planes 2*128*68*4=69632 + zf 128*132*4=67584 + bias 4096 = 141,312 B
    size_t smemB = (size_t)(2 * MPAD * PHW * 4 + MPAD * ZW * 4 + 4096);
    cudaFuncSetAttribute(gnn_mma_kernel, cudaFuncAttributeMaxDynamicSharedMemorySize, (int)smemB);
    gnn_mma_kernel<<<nblk, NTHREADS, smemB>>>(bmsg, Wout, bout, out);
}

// round 16
// speedup vs baseline: 1.1847x; 1.1847x over previous
#include <cuda_runtime.h>
#include <cuda_bf16.h>
#include <cstdint>

#define NN 13
#define HD 128
#define NLAYER 8
#define NJ 17
#define DMAX 33
#define OBSD 348
#define SPC 4                  // samples per CTA (kernel B)
#define MREAL 52               // SPC*NN
#define MPAD 64
#define NTHREADS 512
#define PHW 132                // plane row stride (u32): 64 x + 64 agg + 4 pad; 132%32=4
#define HHW 68
#define BTOT 16384

// fragment-packed bf16 hi/lo W images: uint4 = {Bh0,Bh1,Bl0,Bl1} per (k16,n8,lane)
__device__ __align__(16) uint4 g_Bfrag[NLAYER][16 * 16 * 32];
__device__ __align__(16) uint4 g_W2frag[NN][8 * 16 * 32];
__device__ __align__(16) uint32_t g_xh[(size_t)BTOT * NN * 64];
__device__ __align__(16) uint32_t g_xl[(size_t)BTOT * NN * 64];

__constant__ int c_feat[NN][DMAX] = {
  {0,1,2,3,4,22,23,24,25,26,27,45,46,47,48,49,50,51,52,53,54,175,176,177,178,179,180,270,271,272,273,274,275},
  {5,6,28,29,55,56,57,58,59,60,61,62,63,64,181,182,183,184,185,186,276,277,278,279,280,281,0,0,0,0,0,0,0},
  {7,30,65,66,67,68,69,70,71,72,73,74,187,188,189,190,191,192,253,254,255,282,283,284,285,286,287,0,0,0,0,0,0},
  {8,9,10,11,31,32,33,34,75,76,77,78,79,80,81,82,83,84,193,194,195,196,197,198,256,257,258,288,289,290,291,292,293},
  {11,34,85,86,87,88,89,90,91,92,93,94,199,200,201,202,203,204,259,294,295,296,297,298,299,0,0,0,0,0,0,0,0},
  {95,96,97,98,99,100,101,102,103,104,205,206,207,208,209,210,300,301,302,303,304,305,0,0,0,0,0,0,0,0,0,0,0},
  {12,13,14,15,35,36,37,38,105,106,107,108,109,110,111,112,113,114,211,212,213,214,215,216,260,261,262,306,307,308,309,310,311},
  {15,38,115,116,117,118,119,120,121,122,123,124,217,218,219,220,221,222,263,312,313,314,315,316,317,0,0,0,0,0,0,0,0},
  {125,126,127,128,129,130,131,132,133,134,223,224,225,226,227,228,318,319,320,321,322,323,0,0,0,0,0,0,0,0,0,0,0},
  {16,17,18,39,40,41,135,136,137,138,139,140,141,142,143,144,229,230,231,232,233,234,264,265,324,325,326,327,328,329,0,0,0},
  {18,41,145,146,147,148,149,150,151,152,153,154,235,236,237,238,239,240,266,330,331,332,333,334,335,0,0,0,0,0,0,0,0},
  {19,20,21,42,43,44,155,156,157,158,159,160,161,162,163,164,241,242,243,244,245,246,267,268,336,337,338,339,340,341,0,0,0},
  {21,44,165,166,167,168,169,170,171,172,173,174,247,248,249,250,251,252,269,342,343,344,345,346,347,0,0,0,0,0,0,0,0}
};
__constant__ int c_dcnt[NN] = {33,26,27,33,25,22,33,25,22,30,25,30,25};
__constant__ int c_nbr[NN][3] = {
  {1,9,11},{0,2,0},{1,3,6},{2,4,0},{3,5,0},{4,0,0},{2,7,0},
  {6,8,0},{7,0,0},{0,10,0},{9,0,0},{0,12,0},{11,0,0}
};
__constant__ int c_deg[NN] = {3,2,3,2,2,1,2,2,1,2,1,2,1};
__constant__ int c_jm0[NJ] = {1,1,1,2,2,2,3,2,2,2,6,0,0,9,0,0,11};
__constant__ int c_jm1[NJ] = {2,2,2,3,3,3,4,6,6,6,7,9,9,10,11,11,12};

__device__ __forceinline__ float eluf(float x) { return x > 0.0f ? x : expm1f(x); }
__device__ __forceinline__ unsigned long long pk2(float lo, float hi) {
    unsigned long long r;
    asm("mov.b64 %0, {%1, %2};" : "=l"(r) : "f"(lo), "f"(hi));
    return r;
}
__device__ __forceinline__ void upk2(unsigned long long v, float& lo, float& hi) {
    asm("mov.b64 {%0, %1}, %2;" : "=f"(lo), "=f"(hi) : "l"(v));
}
__device__ __forceinline__ void fma2(unsigned long long& d, unsigned long long a, unsigned long long b) {
    asm("fma.rn.f32x2 %0, %1, %2, %0;" : "+l"(d) : "l"(a), "l"(b));
}
__device__ __forceinline__ uint32_t cvt_bf16x2(float hi, float lo) {
    uint32_t r;
    asm("cvt.rn.bf16x2.f32 %0, %1, %2;" : "=r"(r) : "f"(hi), "f"(lo));
    return r;
}
__device__ __forceinline__ void split_pair(float2 f, uint32_t& hi, uint32_t& lo) {
    uint32_t u0 = __float_as_uint(f.x), u1 = __float_as_uint(f.y);
    hi = __byte_perm(u0, u1, 0x7632);
    float r0 = f.x - __uint_as_float(u0 & 0xFFFF0000u);
    float r1 = f.y - __uint_as_float(u1 & 0xFFFF0000u);
    lo = cvt_bf16x2(r1, r0);
}
__device__ __forceinline__ float2 rec2(uint32_t h, uint32_t l) {
    float2 fh = __bfloat1622float2(*reinterpret_cast<__nv_bfloat162*>(&h));
    float2 fl = __bfloat1622float2(*reinterpret_cast<__nv_bfloat162*>(&l));
    return make_float2(fh.x + fl.x, fh.y + fl.y);
}
__device__ __forceinline__ void mma_bf16(float* c, const uint32_t* a, uint32_t b0, uint32_t b1) {
    asm("mma.sync.aligned.m16n8k16.row.col.f32.bf16.bf16.f32 "
        "{%0,%1,%2,%3}, {%4,%5,%6,%7}, {%8,%9}, {%0,%1,%2,%3};"
        : "+f"(c[0]), "+f"(c[1]), "+f"(c[2]), "+f"(c[3])
        : "r"(a[0]), "r"(a[1]), "r"(a[2]), "r"(a[3]), "r"(b0), "r"(b1));
}
__device__ __forceinline__ void ldsm4(uint32_t* r, uint32_t addr) {
    asm volatile("ldmatrix.sync.aligned.m8n8.x4.shared.b16 {%0,%1,%2,%3}, [%4];"
        : "=r"(r[0]), "=r"(r[1]), "=r"(r[2]), "=r"(r[3]) : "r"(addr));
}
__device__ __forceinline__ void cpa16(uint32_t s, const void* g) {
    asm volatile("cp.async.cg.shared.global [%0], [%1], 16;\n" :: "r"(s), "l"(g));
}
__device__ __forceinline__ void cpa_commit() { asm volatile("cp.async.commit_group;\n" ::: "memory"); }
__device__ __forceinline__ void cpa_wait0()  { asm volatile("cp.async.wait_group 0;\n" ::: "memory"); }

// ======== prep kernels (layouts unchanged) ========
__global__ void prep_kernel(const float* __restrict__ Wmsg) {
    int idx = blockIdx.x * 256 + threadIdx.x;
    int lane = idx & 31;
    int nt   = (idx >> 5) & 15;
    int k16  = (idx >> 9) & 15;
    int l    = idx >> 13;
    if (l >= NLAYER) return;
    int n  = nt * 8 + (lane >> 2);
    int q2 = (lane & 3) * 2;
    int kb = k16 * 16;
    const float* W = Wmsg + (size_t)l * 256 * HD;
    float w0 = W[(kb + q2) * HD + n];
    float w1 = W[(kb + q2 + 1) * HD + n];
    float w2 = W[(kb + 8 + q2) * HD + n];
    float w3 = W[(kb + 8 + q2 + 1) * HD + n];
    __nv_bfloat162 h0 = __floats2bfloat162_rn(w0, w1);
    __nv_bfloat162 h1 = __floats2bfloat162_rn(w2, w3);
    __nv_bfloat162 l0 = __floats2bfloat162_rn(w0 - __bfloat162float(h0.x), w1 - __bfloat162float(h0.y));
    __nv_bfloat162 l1 = __floats2bfloat162_rn(w2 - __bfloat162float(h1.x), w3 - __bfloat162float(h1.y));
    uint4 v;
    v.x = *reinterpret_cast<uint32_t*>(&h0);
    v.y = *reinterpret_cast<uint32_t*>(&h1);
    v.z = *reinterpret_cast<uint32_t*>(&l0);
    v.w = *reinterpret_cast<uint32_t*>(&l1);
    g_Bfrag[l][(k16 * 16 + nt) * 32 + lane] = v;
}
__global__ void prep2_kernel(const float* __restrict__ W2) {
    int idx = blockIdx.x * 256 + threadIdx.x;
    int lane = idx & 31;
    int nt   = (idx >> 5) & 15;
    int k16  = (idx >> 9) & 7;
    int n    = idx >> 12;
    if (n >= NN) return;
    int nc = nt * 8 + (lane >> 2);
    int q2 = (lane & 3) * 2;
    int kb = k16 * 16;
    const float* W = W2 + (size_t)n * HD * HD;
    float w0 = W[(kb + q2) * HD + nc];
    float w1 = W[(kb + q2 + 1) * HD + nc];
    float w2 = W[(kb + 8 + q2) * HD + nc];
    float w3 = W[(kb + 8 + q2 + 1) * HD + nc];
    __nv_bfloat162 h0 = __floats2bfloat162_rn(w0, w1);
    __nv_bfloat162 h1 = __floats2bfloat162_rn(w2, w3);
    __nv_bfloat162 l0 = __floats2bfloat162_rn(w0 - __bfloat162float(h0.x), w1 - __bfloat162float(h0.y));
    __nv_bfloat162 l1 = __floats2bfloat162_rn(w2 - __bfloat162float(h1.x), w3 - __bfloat162float(h1.y));
    uint4 v;
    v.x = *reinterpret_cast<uint32_t*>(&h0);
    v.y = *reinterpret_cast<uint32_t*>(&h1);
    v.z = *reinterpret_cast<uint32_t*>(&l0);
    v.w = *reinterpret_cast<uint32_t*>(&l1);
    g_W2frag[n][(k16 * 16 + nt) * 32 + lane] = v;
}

// ======== kernel A: encoder (unchanged from R14) ========
__global__ __launch_bounds__(NTHREADS, 1)
void enc_kernel(const float* __restrict__ obs,
                const float* __restrict__ W1, const float* __restrict__ b1,
                const float* __restrict__ b2)
{
    extern __shared__ __align__(16) uint32_t smu[];
    uint32_t* hh = smu;
    uint32_t* hl = smu + 128 * HHW;
    float* xn = (float*)(smu + 2 * 128 * HHW);

    const int tid  = threadIdx.x;
    const int lane = tid & 31;
    const int ty   = tid >> 5;
    const int n    = blockIdx.x >> 7;
    const int s0   = (blockIdx.x & 127) * 128;

    const uint32_t hh_a = (uint32_t)__cvta_generic_to_shared(hh);
    const uint32_t hl_a = (uint32_t)__cvta_generic_to_shared(hl);

    const int dc = c_dcnt[n];
    for (int i = tid; i < 128 * dc; i += NTHREADS) {
        int s = i / dc, d = i - s * dc;
        xn[s * 36 + d] = obs[(size_t)(s0 + s) * OBSD + c_feat[n][d]];
    }
    __syncthreads();

    {
        unsigned long long acc[8][2];
        const unsigned long long* bp = (const unsigned long long*)(b1 + n * HD);
        unsigned long long a0 = bp[lane], a1 = bp[lane + 32];
        #pragma unroll
        for (int s = 0; s < 8; ++s) { acc[s][0] = a0; acc[s][1] = a1; }
        #pragma unroll 1
        for (int d = 0; d < dc; ++d) {
            const unsigned long long* wr = (const unsigned long long*)(W1 + (n * DMAX + d) * HD);
            unsigned long long w0 = wr[lane], w1 = wr[lane + 32];
            #pragma unroll
            for (int s = 0; s < 8; ++s) {
                float xe = xn[(ty * 8 + s) * 36 + d];
                unsigned long long p = pk2(xe, xe);
                fma2(acc[s][0], p, w0); fma2(acc[s][1], p, w1);
            }
        }
        #pragma unroll
        for (int s = 0; s < 8; ++s) {
            const int row = ty * 8 + s;
            float lo, hi;
            uint32_t ph, pl;
            upk2(acc[s][0], lo, hi);
            split_pair(make_float2(eluf(lo), eluf(hi)), ph, pl);
            hh[row * HHW + lane] = ph; hl[row * HHW + lane] = pl;
            upk2(acc[s][1], lo, hi);
            split_pair(make_float2(eluf(lo), eluf(hi)), ph, pl);
            hh[row * HHW + 32 + lane] = ph; hl[row * HHW + 32 + lane] = pl;
        }
    }
    __syncthreads();

    const int mwarp = ty >> 2;
    const int nwarp = ty & 3;
    const int qr = lane >> 2;
    const int q2c = lane & 3;

    uint32_t lb_h[2], lb_l[2];
    {
        int seg = lane >> 3, rr = lane & 7;
        #pragma unroll
        for (int t = 0; t < 2; ++t) {
            int row = mwarp * 32 + t * 16 + (seg & 1) * 8 + rr;
            uint32_t off = (uint32_t)row * (HHW * 4) + (uint32_t)(seg >> 1) * 16;
            lb_h[t] = hh_a + off;
            lb_l[t] = hl_a + off;
        }
    }

    float C[2][4][4];
    #pragma unroll
    for (int t = 0; t < 2; ++t)
        #pragma unroll
        for (int nt = 0; nt < 4; ++nt)
            #pragma unroll
            for (int e = 0; e < 4; ++e) C[t][nt][e] = 0.0f;

    const uint4* Bf = g_W2frag[n];
    #pragma unroll 1
    for (int k16 = 0; k16 < 8; ++k16) {
        const uint32_t kboff = (uint32_t)k16 * 32;
        uint32_t Ah[2][4], Al[2][4];
        #pragma unroll
        for (int t = 0; t < 2; ++t) {
            ldsm4(Ah[t], lb_h[t] + kboff);
            ldsm4(Al[t], lb_l[t] + kboff);
        }
        #pragma unroll
        for (int nt = 0; nt < 4; ++nt) {
            uint4 bv = Bf[(k16 * 16 + nwarp * 4 + nt) * 32 + lane];
            #pragma unroll
            for (int t = 0; t < 2; ++t) {
                mma_bf16(C[t][nt], Ah[t], bv.x, bv.y);
                mma_bf16(C[t][nt], Al[t], bv.x, bv.y);
                mma_bf16(C[t][nt], Ah[t], bv.z, bv.w);
            }
        }
    }
    #pragma unroll
    for (int t = 0; t < 2; ++t) {
        const int r0 = mwarp * 32 + t * 16 + qr;
        #pragma unroll
        for (int nt = 0; nt < 4; ++nt) {
            const int c2 = nwarp * 16 + nt * 4 + q2c;
            float2 bb = *(const float2*)(b2 + n * HD + 2 * c2);
            uint32_t ph, pl;
            size_t ga = ((size_t)(s0 + r0) * NN + n) * 64 + c2;
            split_pair(make_float2(C[t][nt][0] + bb.x, C[t][nt][1] + bb.y), ph, pl);
            g_xh[ga] = ph; g_xl[ga] = pl;
            size_t gb = ((size_t)(s0 + r0 + 8) * NN + n) * 64 + c2;
            split_pair(make_float2(C[t][nt][2] + bb.x, C[t][nt][3] + bb.y), ph, pl);
            g_xh[gb] = ph; g_xl[gb] = pl;
        }
    }
}

// ======== kernel B: message passing, M=64 tile, 2 CTAs/SM ========
__global__ __launch_bounds__(NTHREADS, 2)
void gnn_mma_kernel(const float* __restrict__ bmsg,
                    const float* __restrict__ Wout, const float* __restrict__ bout,
                    float* __restrict__ out)
{
    extern __shared__ __align__(16) uint32_t smu[];
    uint32_t* xh = smu;                       // [64][132] u32: cols 0..63 x, 64..127 agg
    uint32_t* xl = smu + MPAD * PHW;
    float* sbias = (float*)(smu + 2 * MPAD * PHW);   // 1024 floats

    const int tid  = threadIdx.x;
    const int lane = tid & 31;
    const int ty   = tid >> 5;                // warp 0..15
    const int base_s = blockIdx.x * SPC;

    const uint32_t xh_a = (uint32_t)__cvta_generic_to_shared(xh);
    const uint32_t xl_a = (uint32_t)__cvta_generic_to_shared(xl);

    // ==== load x0 planes (52 rows x 64 u32) + bias + zero pads ====
    {
        const uint32_t* gh = g_xh + (size_t)base_s * NN * 64;
        const uint32_t* gl = g_xl + (size_t)base_s * NN * 64;
        for (int i = tid; i < MREAL * 16; i += NTHREADS) {
            int r = i >> 4, c4 = (i & 15) * 4;
            cpa16(xh_a + (uint32_t)(r * PHW + c4) * 4, gh + r * 64 + c4);
            cpa16(xl_a + (uint32_t)(r * PHW + c4) * 4, gl + r * 64 + c4);
        }
        cpa_commit();
        if (tid < 256) ((float4*)sbias)[tid] = ((const float4*)bmsg)[tid];
        for (int i = tid; i < (MPAD - MREAL) * PHW; i += NTHREADS) {
            xh[MREAL * PHW + i] = 0u;
            xl[MREAL * PHW + i] = 0u;
        }
    }
    cpa_wait0();

    const int mwarp = ty >> 3;                // 0..1  (32 rows each)
    const int nwarp = ty & 7;                 // 0..7  (16 cols each)
    const int qr = lane >> 2;
    const int q2c = lane & 3;

    uint32_t lbase_h[2], lbase_l[2];
    {
        int seg = lane >> 3, rr = lane & 7;
        #pragma unroll
        for (int t = 0; t < 2; ++t) {
            int row = mwarp * 32 + t * 16 + (seg & 1) * 8 + rr;
            uint32_t off = (uint32_t)row * (PHW * 4) + (uint32_t)(seg >> 1) * 16;
            lbase_h[t] = xh_a + off;
            lbase_l[t] = xl_a + off;
        }
    }

    for (int l = 0; l < NLAYER; ++l) {
        const uint4* Bl = g_Bfrag[l];

        __syncthreads();   // x planes ready (initial load or previous epilogue)
        // aggregation: read x (u32 cols 0..63), write agg (64..127)
        for (int i = tid; i < MREAL * 64; i += NTHREADS) {
            int c = i & 63;
            int m = i >> 6;
            int n = m % NN;
            int s13 = m - n;
            int r0 = (s13 + c_nbr[n][0]) * PHW + c;
            float2 sum = rec2(xh[r0], xl[r0]);
            int dg = c_deg[n];
            if (dg > 1) {
                int r1 = (s13 + c_nbr[n][1]) * PHW + c;
                float2 v = rec2(xh[r1], xl[r1]);
                sum.x += v.x; sum.y += v.y;
            }
            if (dg > 2) {
                int r2 = (s13 + c_nbr[n][2]) * PHW + c;
                float2 v = rec2(xh[r2], xl[r2]);
                sum.x += v.x; sum.y += v.y;
            }
            uint32_t ph, pl;
            split_pair(sum, ph, pl);
            xh[m * PHW + 64 + c] = ph;
            xl[m * PHW + 64 + c] = pl;
        }
        __syncthreads();   // agg visible

        float C[2][2][4];
        #pragma unroll
        for (int t = 0; t < 2; ++t)
            #pragma unroll
            for (int nt = 0; nt < 2; ++nt)
                #pragma unroll
                for (int e = 0; e < 4; ++e) C[t][nt][e] = 0.0f;

        #pragma unroll 2
        for (int k16 = 0; k16 < 16; ++k16) {
            const uint32_t kboff = (uint32_t)k16 * 32;     // 16 bf16 = 32 bytes
            uint32_t Ah[2][4], Al[2][4];
            #pragma unroll
            for (int t = 0; t < 2; ++t) {
                ldsm4(Ah[t], lbase_h[t] + kboff);
                ldsm4(Al[t], lbase_l[t] + kboff);
            }
            #pragma unroll
            for (int nt = 0; nt < 2; ++nt) {
                uint4 bv = Bl[(k16 * 16 + nwarp * 2 + nt) * 32 + lane];
                #pragma unroll
                for (int t = 0; t < 2; ++t) {
                    mma_bf16(C[t][nt], Ah[t], bv.x, bv.y);
                    mma_bf16(C[t][nt], Al[t], bv.x, bv.y);
                    mma_bf16(C[t][nt], Ah[t], bv.z, bv.w);
                }
            }
        }
        // epilogue: x = elu(C + bias) -> x cols
        #pragma unroll
        for (int t = 0; t < 2; ++t) {
            const int r0 = mwarp * 32 + t * 16 + qr;
            #pragma unroll
            for (int nt = 0; nt < 2; ++nt) {
                const int c2 = nwarp * 8 + nt * 4 + q2c;   // u32 col 0..63
                float2 bb = *(const float2*)(sbias + l * HD + 2 * c2);
                uint32_t ph, pl;
                if (r0 < MREAL) {
                    split_pair(make_float2(eluf(C[t][nt][0] + bb.x),
                                           eluf(C[t][nt][1] + bb.y)), ph, pl);
                    xh[r0 * PHW + c2] = ph; xl[r0 * PHW + c2] = pl;
                }
                if (r0 + 8 < MREAL) {
                    split_pair(make_float2(eluf(C[t][nt][2] + bb.x),
                                           eluf(C[t][nt][3] + bb.y)), ph, pl);
                    xh[(r0 + 8) * PHW + c2] = ph; xl[(r0 + 8) * PHW + c2] = pl;
                }
            }
        }
    }
    __syncthreads();

    // ==== joint readout ====
    for (int t = ty; t < SPC * NJ; t += 16) {
        int s = t / NJ, j = t - s * NJ;
        const int ra = (s * NN + c_jm0[j]) * PHW;
        const int rb = (s * NN + c_jm1[j]) * PHW;
        const float* wj = Wout + j * 2 * HD;
        float2 a0 = rec2(xh[ra + lane], xl[ra + lane]);
        float2 a1 = rec2(xh[ra + 32 + lane], xl[ra + 32 + lane]);
        float2 b0 = rec2(xh[rb + lane], xl[rb + lane]);
        float2 b1v = rec2(xh[rb + 32 + lane], xl[rb + 32 + lane]);
        float2 w0 = *(const float2*)(wj + 2 * lane);
        float2 w1 = *(const float2*)(wj + 64 + 2 * lane);
        float2 w2 = *(const float2*)(wj + HD + 2 * lane);
        float2 w3 = *(const float2*)(wj + HD + 64 + 2 * lane);
        float sum = a0.x * w0.x + a0.y * w0.y + a1.x * w1.x + a1.y * w1.y
                  + b0.x * w2.x + b0.y * w2.y + b1v.x * w3.x + b1v.y * w3.y;
        #pragma unroll
        for (int o = 16; o; o >>= 1)
            sum += __shfl_xor_sync(0xffffffffu, sum, o);
        if (lane == 0)
            out[(size_t)(base_s + s) * NJ + j] = sum + bout[j];
    }
}

extern "C" void kernel_launch(void* const* d_in, const int* in_sizes, int n_in,
                              void* d_out, int out_size) {
    const float* obs  = (const float*)d_in[0];
    const float* W1   = (const float*)d_in[1];
    const float* b1   = (const float*)d_in[2];
    const float* W2   = (const float*)d_in[3];
    const float* b2   = (const float*)d_in[4];
    const float* Wmsg = (const float*)d_in[5];
    const float* bmsg = (const float*)d_in[6];
    const float* Wout = (const float*)d_in[7];
    const float* bout = (const float*)d_in[8];
    float* out = (float*)d_out;

    prep_kernel<<<NLAYER * 16 * 16 * 32 / 256, 256>>>(Wmsg);
    prep2_kernel<<<(NN * 8 * 16 * 32 + 255) / 256, 256>>>(W2);

    int B = in_sizes[0] / OBSD;

    size_t smemA = (size_t)(2 * 128 * HHW * 4 + 128 * 36 * 4);   // 88,064 B
    cudaFuncSetAttribute(enc_kernel, cudaFuncAttributeMaxDynamicSharedMemorySize, (int)smemA);
    enc_kernel<<<NN * (B / 128), NTHREADS, smemA>>>(obs, W1, b1, b2);

    int nblk = B / SPC;                              // 4096
    size_t smemB = (size_t)(2 * MPAD * PHW * 4 + 4096);  // 71,680 B -> 2 CTAs/SM
    cudaFuncSetAttribute(gnn_mma_kernel, cudaFuncAttributeMaxDynamicSharedMemorySize, (int)smemB);
    gnn_mma_kernel<<<nblk, NTHREADS, smemB>>>(bmsg, Wout, bout, out);
}